// round 1
// baseline (speedup 1.0000x reference)
#include <cuda_runtime.h>
#include <cuda_bf16.h>
#include <math_constants.h>

#define NN 20000
#define EE 400000
#define TT 8
#define CINC 8
#define HID 16
#define HEADS 4
#define FF 128      // HID*TT
#define HF 512      // HEADS*FF
#define EPSF 1e-5f

// ---------------- scratch (device globals; no allocation allowed) ----------------
__device__ float g_h1[NN * FF];        // gated_conv1 output (pre-bn3)
__device__ float g_res[NN * FF];       // residual
__device__ float g_lin[(size_t)NN * HF]; // GAT linear output [N, 4, 128]
__device__ float g_as[NN * HEADS];
__device__ float g_ad[NN * HEADS];
__device__ float g_hgat[NN * FF];      // GAT output (pre-bn2)
__device__ float g_h2[NN * FF];        // gated_conv2 output (pre-bn3)
__device__ int   g_deg[NN];
__device__ int   g_off[NN + 1];
__device__ int   g_cur[NN];
__device__ int   g_srcsorted[EE];

__device__ double g_s1[HID], g_q1[HID];   // bn3 #1 stats
__device__ double g_s2[FF],  g_q2[FF];    // bn2 stats
__device__ double g_s3[HID], g_q3[HID];   // bn3 #2 stats
__device__ float g_m1[HID], g_r1[HID];
__device__ float g_m2[FF],  g_r2[FF];
__device__ float g_m3[HID], g_r3[HID];

// ---------------- K0: zero scratch ----------------
__global__ void k0_zero() {
    int i = blockIdx.x * 256 + threadIdx.x;
    if (i < NN) { g_deg[i] = 0; g_cur[i] = 0; }
    if (i < HID) { g_s1[i] = 0.0; g_q1[i] = 0.0; g_s3[i] = 0.0; g_q3[i] = 0.0; }
    if (i < FF)  { g_s2[i] = 0.0; g_q2[i] = 0.0; }
}

// ---------------- K1: pointwise + residual + gated_conv1 + bn3 stats ----------------
// 4 warps/block, 1 warp per node. lane l: t = l&7, o0 = l>>3, handles o = o0+4j.
__global__ void k1_front(const float* __restrict__ X,
                         const float* __restrict__ w_in, const float* __restrict__ b_in,
                         const float* __restrict__ res_w, const float* __restrict__ res_b,
                         const float* __restrict__ w1, const float* __restrict__ b1,
                         const float* __restrict__ w2, const float* __restrict__ b2,
                         const float* __restrict__ w3, const float* __restrict__ b3) {
    __shared__ float s_win[HID * CINC], s_bin[HID];
    __shared__ float s_rw[HID * HID], s_rb[HID];
    __shared__ float s_w1[HID * HID * 3], s_w2[HID * HID * 3], s_w3[HID * HID * 3];
    __shared__ float s_b1[HID], s_b2[HID], s_b3[HID];
    __shared__ float s_x[4][HID][TT];
    __shared__ float s_X[4][CINC][TT];
    __shared__ float s_sum[HID], s_sq[HID];

    int tid = threadIdx.x;
    for (int i = tid; i < HID * CINC; i += 128) s_win[i] = w_in[i];
    for (int i = tid; i < HID * HID; i += 128) s_rw[i] = res_w[i];
    for (int i = tid; i < HID * HID * 3; i += 128) {
        s_w1[i] = w1[i]; s_w2[i] = w2[i]; s_w3[i] = w3[i];
    }
    if (tid < HID) {
        s_bin[tid] = b_in[tid]; s_rb[tid] = res_b[tid];
        s_b1[tid] = b1[tid]; s_b2[tid] = b2[tid]; s_b3[tid] = b3[tid];
        s_sum[tid] = 0.f; s_sq[tid] = 0.f;
    }
    __syncthreads();

    int w = tid >> 5, l = tid & 31;
    int n = blockIdx.x * 4 + w;
    int t = l & 7, o0 = l >> 3;

    if (n < NN) {
        const float* Xp = X + (size_t)n * CINC * TT;
        s_X[w][l >> 3][l & 7] = Xp[l];
        s_X[w][(l + 32) >> 3][(l + 32) & 7] = Xp[l + 32];
        __syncwarp();

        // pointwise x = W_in * X + b_in
        #pragma unroll
        for (int j = 0; j < 4; j++) {
            int o = o0 + 4 * j;
            float acc = s_bin[o];
            #pragma unroll
            for (int c = 0; c < CINC; c++) acc += s_X[w][c][t] * s_win[o * CINC + c];
            s_x[w][o][t] = acc;
        }
        __syncwarp();

        // residual
        #pragma unroll
        for (int j = 0; j < 4; j++) {
            int o = o0 + 4 * j;
            float acc = s_rb[o];
            #pragma unroll
            for (int i = 0; i < HID; i++) acc += s_x[w][i][t] * s_rw[o * HID + i];
            g_res[(size_t)n * FF + o * TT + t] = acc;
        }

        // three SAME convs (k=3) + gate
        #pragma unroll
        for (int j = 0; j < 4; j++) {
            int o = o0 + 4 * j;
            float p = s_b1[o], q = s_b2[o], r = s_b3[o];
            #pragma unroll
            for (int i = 0; i < HID; i++) {
                #pragma unroll
                for (int k = 0; k < 3; k++) {
                    int tt = t - 1 + k;
                    if (tt >= 0 && tt < TT) {
                        float xv = s_x[w][i][tt];
                        int wi = (o * HID + i) * 3 + k;
                        p += s_w1[wi] * xv;
                        q += s_w2[wi] * xv;
                        r += s_w3[wi] * xv;
                    }
                }
            }
            float sg = 1.f / (1.f + __expf(-q));
            float h = p * sg + r;
            h = h > 0.f ? h : 0.f;
            g_h1[(size_t)n * FF + o * TT + t] = h;
            atomicAdd(&s_sum[o], h);
            atomicAdd(&s_sq[o], h * h);
        }
    }
    __syncthreads();
    if (tid < HID) {
        atomicAdd(&g_s1[tid], (double)s_sum[tid]);
        atomicAdd(&g_q1[tid], (double)s_sq[tid]);
    }
}

// ---------------- finalize BN stats ----------------
__global__ void k_fin(int mode) {
    int i = threadIdx.x;
    if (mode == 0 && i < HID) {
        double c = (double)NN * TT;
        double mu = g_s1[i] / c;
        double va = g_q1[i] / c - mu * mu;
        g_m1[i] = (float)mu; g_r1[i] = (float)rsqrt(va + 1e-5);
    }
    if (mode == 1 && i < FF) {
        double c = (double)NN;
        double mu = g_s2[i] / c;
        double va = g_q2[i] / c - mu * mu;
        g_m2[i] = (float)mu; g_r2[i] = (float)rsqrt(va + 1e-5);
    }
    if (mode == 2 && i < HID) {
        double c = (double)NN * TT;
        double mu = g_s3[i] / c;
        double va = g_q3[i] / c - mu * mu;
        g_m3[i] = (float)mu; g_r3[i] = (float)rsqrt(va + 1e-5);
    }
}

// ---------------- K2: lin = bn3(h1) @ gat_w  (64x64 tile, 256 thr, 4x4 micro) ----------------
__global__ void k2_gemm(const float* __restrict__ Wg) {
    __shared__ __align__(16) float As[64][68];  // [k][m] (transposed)
    __shared__ __align__(16) float Bs[64][68];  // [k][col]
    __shared__ float sm1[HID], sr1[HID];

    int tid = threadIdx.x;
    if (tid < HID) { sm1[tid] = g_m1[tid]; sr1[tid] = g_r1[tid]; }
    __syncthreads();

    int cb = blockIdx.x * 64;  // output column base (of 512)
    int nb = blockIdx.y * 64;  // node base

    float acc[4][4] = {};
    for (int kb = 0; kb < FF; kb += 64) {
        #pragma unroll
        for (int i = 0; i < 16; i++) {
            int lin = i * 256 + tid;
            int r = lin >> 6, c = lin & 63;
            int n = nb + r, k = kb + c;
            float va = 0.f;
            if (n < NN) {
                float h = g_h1[(size_t)n * FF + k];
                int ch = k >> 3;
                va = (h - sm1[ch]) * sr1[ch];
            }
            As[c][r] = va;
            Bs[r][c] = Wg[(size_t)(kb + r) * HF + cb + c];
        }
        __syncthreads();

        int tx = tid & 15, ty = tid >> 4;
        int m0 = ty * 4, c0 = tx * 4;
        #pragma unroll
        for (int kk = 0; kk < 64; kk++) {
            float4 a = *(const float4*)&As[kk][m0];
            float4 b = *(const float4*)&Bs[kk][c0];
            acc[0][0] += a.x * b.x; acc[0][1] += a.x * b.y; acc[0][2] += a.x * b.z; acc[0][3] += a.x * b.w;
            acc[1][0] += a.y * b.x; acc[1][1] += a.y * b.y; acc[1][2] += a.y * b.z; acc[1][3] += a.y * b.w;
            acc[2][0] += a.z * b.x; acc[2][1] += a.z * b.y; acc[2][2] += a.z * b.z; acc[2][3] += a.z * b.w;
            acc[3][0] += a.w * b.x; acc[3][1] += a.w * b.y; acc[3][2] += a.w * b.z; acc[3][3] += a.w * b.w;
        }
        __syncthreads();
    }

    int tx = tid & 15, ty = tid >> 4;
    int m0 = ty * 4, c0 = tx * 4;
    #pragma unroll
    for (int i = 0; i < 4; i++) {
        int n = nb + m0 + i;
        if (n < NN) {
            float4 v = make_float4(acc[i][0], acc[i][1], acc[i][2], acc[i][3]);
            *(float4*)&g_lin[(size_t)n * HF + cb + c0] = v;
        }
    }
}

// ---------------- K2b: attention scores a_s, a_d ----------------
__global__ void k2b_att(const float* __restrict__ att_s, const float* __restrict__ att_d) {
    int n = blockIdx.x;
    int tid = threadIdx.x;  // 128
    int lane = tid & 31, warp = tid >> 5;
    float ps[HEADS], pd[HEADS];
    #pragma unroll
    for (int j = 0; j < HEADS; j++) {
        float v = g_lin[(size_t)n * HF + j * FF + tid];
        ps[j] = v * att_s[j * FF + tid];
        pd[j] = v * att_d[j * FF + tid];
    }
    #pragma unroll
    for (int j = 0; j < HEADS; j++)
        for (int off = 16; off; off >>= 1) {
            ps[j] += __shfl_down_sync(0xffffffffu, ps[j], off);
            pd[j] += __shfl_down_sync(0xffffffffu, pd[j], off);
        }
    __shared__ float sp[4][HEADS], sd[4][HEADS];
    if (lane == 0)
        #pragma unroll
        for (int j = 0; j < HEADS; j++) { sp[warp][j] = ps[j]; sd[warp][j] = pd[j]; }
    __syncthreads();
    if (tid < HEADS) {
        g_as[n * HEADS + tid] = sp[0][tid] + sp[1][tid] + sp[2][tid] + sp[3][tid];
        g_ad[n * HEADS + tid] = sd[0][tid] + sd[1][tid] + sd[2][tid] + sd[3][tid];
    }
}

// ---------------- K3: CSR build ----------------
__global__ void k3a_hist(const int* __restrict__ ei) {
    int e = blockIdx.x * 256 + threadIdx.x;
    if (e < EE) atomicAdd(&g_deg[ei[EE + e]], 1);
}

__global__ void k3b_scan() {
    __shared__ int ps[1024];
    int tid = threadIdx.x;
    const int chunk = (NN + 1023) / 1024;  // 20
    int start = tid * chunk;
    int end = min(start + chunk, NN);
    int s = 0;
    for (int i = start; i < end; i++) s += g_deg[i];
    ps[tid] = s;
    __syncthreads();
    for (int d = 1; d < 1024; d <<= 1) {
        int v = 0;
        if (tid >= d) v = ps[tid - d];
        __syncthreads();
        if (tid >= d) ps[tid] += v;
        __syncthreads();
    }
    int run = ps[tid] - s;  // exclusive base
    for (int i = start; i < end; i++) { g_off[i] = run; run += g_deg[i]; }
    if (tid == 0) g_off[NN] = ps[1023];
}

__global__ void k3c_scatter(const int* __restrict__ ei) {
    int e = blockIdx.x * 256 + threadIdx.x;
    if (e < EE) {
        int d = ei[EE + e];
        int slot = g_off[d] + atomicAdd(&g_cur[d], 1);
        g_srcsorted[slot] = ei[e];
    }
}

// ---------------- K4: GAT aggregation (block per dst) + bn2 stats ----------------
__global__ void k4_gat(const float* __restrict__ gat_b) {
    int n = blockIdx.x;
    int tid = threadIdx.x;  // 128
    int lane = tid & 31, warp = tid >> 5;
    int beg = g_off[n], end = g_off[n + 1];

    __shared__ float s_mh[HEADS], s_sh[HEADS];
    __shared__ float s_red[HEADS][4];
    __shared__ int sh_src[128];
    __shared__ float sh_al[128][HEADS];

    float ad[HEADS];
    #pragma unroll
    for (int j = 0; j < HEADS; j++) ad[j] = g_ad[n * HEADS + j];

    // pass 1: per-head max
    float mx[HEADS];
    #pragma unroll
    for (int j = 0; j < HEADS; j++) mx[j] = -3.402823466e38f;
    for (int i = beg + tid; i < end; i += 128) {
        int s = g_srcsorted[i];
        #pragma unroll
        for (int j = 0; j < HEADS; j++) {
            float e = g_as[s * HEADS + j] + ad[j];
            e = e > 0.f ? e : 0.2f * e;
            mx[j] = fmaxf(mx[j], e);
        }
    }
    #pragma unroll
    for (int j = 0; j < HEADS; j++)
        for (int off = 16; off; off >>= 1)
            mx[j] = fmaxf(mx[j], __shfl_down_sync(0xffffffffu, mx[j], off));
    if (lane == 0)
        #pragma unroll
        for (int j = 0; j < HEADS; j++) s_red[j][warp] = mx[j];
    __syncthreads();
    if (tid < HEADS)
        s_mh[tid] = fmaxf(fmaxf(s_red[tid][0], s_red[tid][1]),
                          fmaxf(s_red[tid][2], s_red[tid][3]));
    __syncthreads();

    // pass 2: per-head sum of exp
    float sm[HEADS] = {0.f, 0.f, 0.f, 0.f};
    for (int i = beg + tid; i < end; i += 128) {
        int s = g_srcsorted[i];
        #pragma unroll
        for (int j = 0; j < HEADS; j++) {
            float e = g_as[s * HEADS + j] + ad[j];
            e = e > 0.f ? e : 0.2f * e;
            sm[j] += __expf(e - s_mh[j]);
        }
    }
    #pragma unroll
    for (int j = 0; j < HEADS; j++)
        for (int off = 16; off; off >>= 1)
            sm[j] += __shfl_down_sync(0xffffffffu, sm[j], off);
    __syncthreads();  // protect s_red reuse
    if (lane == 0)
        #pragma unroll
        for (int j = 0; j < HEADS; j++) s_red[j][warp] = sm[j];
    __syncthreads();
    if (tid < HEADS)
        s_sh[tid] = s_red[tid][0] + s_red[tid][1] + s_red[tid][2] + s_red[tid][3] + 1e-16f;
    __syncthreads();

    // pass 3: alpha-weighted gather, chunked through shared
    float a0 = 0.f, a1 = 0.f, a2 = 0.f, a3 = 0.f;
    for (int base = beg; base < end; base += 128) {
        int i = base + tid;
        if (i < end) {
            int s = g_srcsorted[i];
            sh_src[tid] = s;
            #pragma unroll
            for (int j = 0; j < HEADS; j++) {
                float e = g_as[s * HEADS + j] + ad[j];
                e = e > 0.f ? e : 0.2f * e;
                sh_al[tid][j] = __expf(e - s_mh[j]) / s_sh[j];
            }
        }
        __syncthreads();
        int cnt = min(128, end - base);
        for (int k = 0; k < cnt; k++) {
            int s = sh_src[k];
            const float* lp = &g_lin[(size_t)s * HF];
            a0 += sh_al[k][0] * lp[tid];
            a1 += sh_al[k][1] * lp[FF + tid];
            a2 += sh_al[k][2] * lp[2 * FF + tid];
            a3 += sh_al[k][3] * lp[3 * FF + tid];
        }
        __syncthreads();
    }

    float v = 0.25f * (a0 + a1 + a2 + a3) + gat_b[tid];
    g_hgat[(size_t)n * FF + tid] = v;
    atomicAdd(&g_s2[tid], (double)v);
    atomicAdd(&g_q2[tid], (double)v * (double)v);
}

// ---------------- K5: bn2-normalize + gated_conv2 + bn3 stats ----------------
__global__ void k5_conv2(const float* __restrict__ w1, const float* __restrict__ b1,
                         const float* __restrict__ w2, const float* __restrict__ b2,
                         const float* __restrict__ w3, const float* __restrict__ b3) {
    __shared__ float s_w1[HID * HID * 3], s_w2[HID * HID * 3], s_w3[HID * HID * 3];
    __shared__ float s_b1[HID], s_b2[HID], s_b3[HID];
    __shared__ float s_m2[FF], s_r2[FF];
    __shared__ float s_x[4][HID][TT];
    __shared__ float s_sum[HID], s_sq[HID];

    int tid = threadIdx.x;
    for (int i = tid; i < HID * HID * 3; i += 128) {
        s_w1[i] = w1[i]; s_w2[i] = w2[i]; s_w3[i] = w3[i];
    }
    if (tid < HID) {
        s_b1[tid] = b1[tid]; s_b2[tid] = b2[tid]; s_b3[tid] = b3[tid];
        s_sum[tid] = 0.f; s_sq[tid] = 0.f;
    }
    if (tid < FF) { s_m2[tid] = g_m2[tid]; s_r2[tid] = g_r2[tid]; }
    __syncthreads();

    int w = tid >> 5, l = tid & 31;
    int n = blockIdx.x * 4 + w;
    int t = l & 7, o0 = l >> 3;

    if (n < NN) {
        // load + normalize input (128 values per node, 4 per lane)
        #pragma unroll
        for (int j = 0; j < 4; j++) {
            int idx = l + 32 * j;  // = o*8+t
            float h = g_hgat[(size_t)n * FF + idx];
            s_x[w][idx >> 3][idx & 7] = (h - s_m2[idx]) * s_r2[idx];
        }
        __syncwarp();

        #pragma unroll
        for (int j = 0; j < 4; j++) {
            int o = o0 + 4 * j;
            float p = s_b1[o], q = s_b2[o], r = s_b3[o];
            #pragma unroll
            for (int i = 0; i < HID; i++) {
                #pragma unroll
                for (int k = 0; k < 3; k++) {
                    int tt = t - 1 + k;
                    if (tt >= 0 && tt < TT) {
                        float xv = s_x[w][i][tt];
                        int wi = (o * HID + i) * 3 + k;
                        p += s_w1[wi] * xv;
                        q += s_w2[wi] * xv;
                        r += s_w3[wi] * xv;
                    }
                }
            }
            float sg = 1.f / (1.f + __expf(-q));
            float h = p * sg + r;
            h = h > 0.f ? h : 0.f;
            g_h2[(size_t)n * FF + o * TT + t] = h;
            atomicAdd(&s_sum[o], h);
            atomicAdd(&s_sq[o], h * h);
        }
    }
    __syncthreads();
    if (tid < HID) {
        atomicAdd(&g_s3[tid], (double)s_sum[tid]);
        atomicAdd(&g_q3[tid], (double)s_sq[tid]);
    }
}

// ---------------- K6: epilogue — bn3 + residual + relu + last-step MLP ----------------
__global__ void k6_out(const float* __restrict__ ow1, const float* __restrict__ ob1,
                       const float* __restrict__ ow2, const float* __restrict__ ob2,
                       float* __restrict__ out) {
    int n = blockIdx.x;
    int tid = threadIdx.x;  // 64
    __shared__ float z[HID];
    __shared__ float ws[2];
    if (tid < HID) {
        size_t idx = (size_t)n * FF + tid * TT + (TT - 1);
        float h = (g_h2[idx] - g_m3[tid]) * g_r3[tid] + g_res[idx];
        z[tid] = h > 0.f ? h : 0.f;
    }
    __syncthreads();
    float y = ob1[tid];
    #pragma unroll
    for (int o = 0; o < HID; o++) y += z[o] * ow1[o * 64 + tid];
    y = y > 0.f ? y : 0.f;
    float contrib = y * ow2[tid];
    for (int off = 16; off; off >>= 1)
        contrib += __shfl_down_sync(0xffffffffu, contrib, off);
    if ((tid & 31) == 0) ws[tid >> 5] = contrib;
    __syncthreads();
    if (tid == 0) out[n] = ws[0] + ws[1] + ob2[0];
}

// ---------------- launch ----------------
extern "C" void kernel_launch(void* const* d_in, const int* in_sizes, int n_in,
                              void* d_out, int out_size) {
    const float* X       = (const float*)d_in[0];
    const int*   ei      = (const int*)  d_in[1];
    const float* w_in    = (const float*)d_in[2];
    const float* b_in    = (const float*)d_in[3];
    const float* res_w   = (const float*)d_in[4];
    const float* res_b   = (const float*)d_in[5];
    const float* tg1_w1  = (const float*)d_in[6];
    const float* tg1_b1  = (const float*)d_in[7];
    const float* tg1_w2  = (const float*)d_in[8];
    const float* tg1_b2  = (const float*)d_in[9];
    const float* tg1_w3  = (const float*)d_in[10];
    const float* tg1_b3  = (const float*)d_in[11];
    const float* gat_w   = (const float*)d_in[12];
    const float* att_src = (const float*)d_in[13];
    const float* att_dst = (const float*)d_in[14];
    const float* gat_b   = (const float*)d_in[15];
    const float* tg2_w1  = (const float*)d_in[16];
    const float* tg2_b1  = (const float*)d_in[17];
    const float* tg2_w2  = (const float*)d_in[18];
    const float* tg2_b2  = (const float*)d_in[19];
    const float* tg2_w3  = (const float*)d_in[20];
    const float* tg2_b3  = (const float*)d_in[21];
    const float* out_w1  = (const float*)d_in[22];
    const float* out_b1  = (const float*)d_in[23];
    const float* out_w2  = (const float*)d_in[24];
    const float* out_b2  = (const float*)d_in[25];
    float* out = (float*)d_out;

    k0_zero<<<(NN + 255) / 256, 256>>>();
    k1_front<<<(NN + 3) / 4, 128>>>(X, w_in, b_in, res_w, res_b,
                                    tg1_w1, tg1_b1, tg1_w2, tg1_b2, tg1_w3, tg1_b3);
    k3a_hist<<<(EE + 255) / 256, 256>>>(ei);
    k3b_scan<<<1, 1024>>>();
    k3c_scatter<<<(EE + 255) / 256, 256>>>(ei);
    k_fin<<<1, 128>>>(0);
    {
        dim3 grid(HF / 64, (NN + 63) / 64);
        k2_gemm<<<grid, 256>>>(gat_w);
    }
    k2b_att<<<NN, 128>>>(att_src, att_dst);
    k4_gat<<<NN, 128>>>(gat_b);
    k_fin<<<1, 128>>>(1);
    k5_conv2<<<(NN + 3) / 4, 128>>>(tg2_w1, tg2_b1, tg2_w2, tg2_b2, tg2_w3, tg2_b3);
    k_fin<<<1, 128>>>(2);
    k6_out<<<NN, 64>>>(out_w1, out_b1, out_w2, out_b2, out);
}

// round 2
// speedup vs baseline: 1.1470x; 1.1470x over previous
#include <cuda_runtime.h>
#include <cuda_bf16.h>
#include <math_constants.h>

#define NN 20000
#define EE 400000
#define TT 8
#define CINC 8
#define HID 16
#define HEADS 4
#define FF 128      // HID*TT
#define HF 512      // HEADS*FF

// ---------------- scratch (device globals) ----------------
__device__ float g_h1[NN * FF];
__device__ float g_res[NN * FF];
__device__ float g_lin[(size_t)NN * HF];
__device__ float g_as[NN * HEADS];
__device__ float g_ad[NN * HEADS];
__device__ float g_hgat[NN * FF];
__device__ float g_h2[NN * FF];
__device__ int   g_deg[NN];
__device__ int   g_off[NN + 1];
__device__ int   g_cur[NN];
__device__ int   g_srcsorted[EE];

__device__ double g_s1[HID], g_q1[HID];
__device__ double g_s2[FF],  g_q2[FF];
__device__ double g_s3[HID], g_q3[HID];
__device__ float g_m1[HID], g_r1[HID];
__device__ float g_m2[FF],  g_r2[FF];
__device__ float g_m3[HID], g_r3[HID];

// ---------------- K0: zero scratch ----------------
__global__ void k0_zero() {
    int i = blockIdx.x * 256 + threadIdx.x;
    if (i < NN) { g_deg[i] = 0; g_cur[i] = 0; }
    if (i < HID) { g_s1[i] = 0.0; g_q1[i] = 0.0; g_s3[i] = 0.0; g_q3[i] = 0.0; }
    if (i < FF)  { g_s2[i] = 0.0; g_q2[i] = 0.0; }
}

// ---------------- K1: pointwise + residual + gated_conv1 + bn3 stats ----------------
__global__ void k1_front(const float* __restrict__ X,
                         const float* __restrict__ w_in, const float* __restrict__ b_in,
                         const float* __restrict__ res_w, const float* __restrict__ res_b,
                         const float* __restrict__ w1, const float* __restrict__ b1,
                         const float* __restrict__ w2, const float* __restrict__ b2,
                         const float* __restrict__ w3, const float* __restrict__ b3) {
    __shared__ float s_win[HID * CINC], s_bin[HID];
    __shared__ float s_rw[HID * HID], s_rb[HID];
    __shared__ float s_w1[HID * HID * 3], s_w2[HID * HID * 3], s_w3[HID * HID * 3];
    __shared__ float s_b1[HID], s_b2[HID], s_b3[HID];
    __shared__ float s_x[4][HID][TT + 2];   // time-padded: index t+1, pads at 0 and 9 are zero
    __shared__ float s_X[4][CINC][TT];
    __shared__ float s_sum[HID], s_sq[HID];

    int tid = threadIdx.x;
    for (int i = tid; i < HID * CINC; i += 128) s_win[i] = w_in[i];
    for (int i = tid; i < HID * HID; i += 128) s_rw[i] = res_w[i];
    for (int i = tid; i < HID * HID * 3; i += 128) {
        s_w1[i] = w1[i]; s_w2[i] = w2[i]; s_w3[i] = w3[i];
    }
    if (tid < HID) {
        s_bin[tid] = b_in[tid]; s_rb[tid] = res_b[tid];
        s_b1[tid] = b1[tid]; s_b2[tid] = b2[tid]; s_b3[tid] = b3[tid];
        s_sum[tid] = 0.f; s_sq[tid] = 0.f;
    }
    __syncthreads();

    int w = tid >> 5, l = tid & 31;
    int n = blockIdx.x * 4 + w;
    int t = l & 7, o0 = l >> 3;

    if (n < NN) {
        if (l < 16) { s_x[w][l][0] = 0.f; s_x[w][l][TT + 1] = 0.f; }
        const float* Xp = X + (size_t)n * CINC * TT;
        s_X[w][l >> 3][l & 7] = Xp[l];
        s_X[w][(l + 32) >> 3][(l + 32) & 7] = Xp[l + 32];
        __syncwarp();

        #pragma unroll
        for (int j = 0; j < 4; j++) {
            int o = o0 + 4 * j;
            float acc = s_bin[o];
            #pragma unroll
            for (int c = 0; c < CINC; c++) acc += s_X[w][c][t] * s_win[o * CINC + c];
            s_x[w][o][t + 1] = acc;
        }
        __syncwarp();

        #pragma unroll
        for (int j = 0; j < 4; j++) {
            int o = o0 + 4 * j;
            float acc = s_rb[o];
            #pragma unroll
            for (int i = 0; i < HID; i++) acc += s_x[w][i][t + 1] * s_rw[o * HID + i];
            g_res[(size_t)n * FF + o * TT + t] = acc;
        }

        #pragma unroll
        for (int j = 0; j < 4; j++) {
            int o = o0 + 4 * j;
            float p = s_b1[o], q = s_b2[o], r = s_b3[o];
            #pragma unroll
            for (int i = 0; i < HID; i++) {
                #pragma unroll
                for (int k = 0; k < 3; k++) {
                    float xv = s_x[w][i][t + k];
                    int wi = (o * HID + i) * 3 + k;
                    p += s_w1[wi] * xv;
                    q += s_w2[wi] * xv;
                    r += s_w3[wi] * xv;
                }
            }
            float sg = 1.f / (1.f + __expf(-q));
            float h = p * sg + r;
            h = h > 0.f ? h : 0.f;
            g_h1[(size_t)n * FF + o * TT + t] = h;
            atomicAdd(&s_sum[o], h);
            atomicAdd(&s_sq[o], h * h);
        }
    }
    __syncthreads();
    if (tid < HID) {
        atomicAdd(&g_s1[tid], (double)s_sum[tid]);
        atomicAdd(&g_q1[tid], (double)s_sq[tid]);
    }
}

// ---------------- finalize BN stats ----------------
__global__ void k_fin(int mode) {
    int i = threadIdx.x;
    if (mode == 0 && i < HID) {
        double c = (double)NN * TT;
        double mu = g_s1[i] / c;
        double va = g_q1[i] / c - mu * mu;
        g_m1[i] = (float)mu; g_r1[i] = (float)rsqrt(va + 1e-5);
    }
    if (mode == 1 && i < FF) {
        double c = (double)NN;
        double mu = g_s2[i] / c;
        double va = g_q2[i] / c - mu * mu;
        g_m2[i] = (float)mu; g_r2[i] = (float)rsqrt(va + 1e-5);
    }
    if (mode == 2 && i < HID) {
        double c = (double)NN * TT;
        double mu = g_s3[i] / c;
        double va = g_q3[i] / c - mu * mu;
        g_m3[i] = (float)mu; g_r3[i] = (float)rsqrt(va + 1e-5);
    }
}

// ---------------- K2: lin = bn3(h1) @ gat_w, fused attention scores ----------------
// 128x128 tile, BK=16, 256 threads, 8x8 micro. One block column == one head.
__global__ void __launch_bounds__(256) k2_gemm(const float* __restrict__ Wg,
                                               const float* __restrict__ att_s,
                                               const float* __restrict__ att_d) {
    __shared__ __align__(16) float As[16][132];   // [k][m]
    __shared__ __align__(16) float Bs[16][132];   // [k][c]
    __shared__ float sm1[HID], sr1[HID];
    __shared__ float sps[128], spd[128];

    int tid = threadIdx.x;
    if (tid < HID) { sm1[tid] = g_m1[tid]; sr1[tid] = g_r1[tid]; }
    __syncthreads();

    int head = blockIdx.x;          // 0..3
    int cb = head * 128;
    int nb = blockIdx.y * 128;
    int tx = tid & 15, ty = tid >> 4;

    float acc[8][8] = {};

    for (int kb = 0; kb < FF; kb += 16) {
        // A tile: 128 rows x 16 k, normalized
        #pragma unroll
        for (int i = 0; i < 2; i++) {
            int id = tid * 2 + i;                // [0,512) float4 ids
            int row = id >> 2, kq = (id & 3) * 4;
            int n = nb + row;
            float4 v = make_float4(0.f, 0.f, 0.f, 0.f);
            if (n < NN) v = *(const float4*)&g_h1[(size_t)n * FF + kb + kq];
            int ch0 = (kb + kq) >> 3;            // 4 consecutive k: channels kq>>3 groups of 8
            As[kq + 0][row] = (v.x - sm1[(kb + kq + 0) >> 3]) * sr1[(kb + kq + 0) >> 3];
            As[kq + 1][row] = (v.y - sm1[(kb + kq + 1) >> 3]) * sr1[(kb + kq + 1) >> 3];
            As[kq + 2][row] = (v.z - sm1[(kb + kq + 2) >> 3]) * sr1[(kb + kq + 2) >> 3];
            As[kq + 3][row] = (v.w - sm1[(kb + kq + 3) >> 3]) * sr1[(kb + kq + 3) >> 3];
            (void)ch0;
        }
        // B tile: 16 k x 128 c
        #pragma unroll
        for (int i = 0; i < 2; i++) {
            int id = tid * 2 + i;
            int k = id >> 5, c = (id & 31) * 4;
            float4 v = *(const float4*)&Wg[(size_t)(kb + k) * HF + cb + c];
            *(float4*)&Bs[k][c] = v;
        }
        __syncthreads();

        #pragma unroll
        for (int kk = 0; kk < 16; kk++) {
            float4 a0 = *(const float4*)&As[kk][ty * 8];
            float4 a1 = *(const float4*)&As[kk][ty * 8 + 4];
            float4 b0 = *(const float4*)&Bs[kk][tx * 8];
            float4 b1 = *(const float4*)&Bs[kk][tx * 8 + 4];
            float av[8] = {a0.x, a0.y, a0.z, a0.w, a1.x, a1.y, a1.z, a1.w};
            float bv[8] = {b0.x, b0.y, b0.z, b0.w, b1.x, b1.y, b1.z, b1.w};
            #pragma unroll
            for (int i = 0; i < 8; i++)
                #pragma unroll
                for (int j = 0; j < 8; j++)
                    acc[i][j] += av[i] * bv[j];
        }
        __syncthreads();
    }

    // attention vectors for this block's 8 columns
    float asv[8], adv[8];
    #pragma unroll
    for (int j = 0; j < 8; j++) {
        asv[j] = att_s[head * FF + tx * 8 + j];
        adv[j] = att_d[head * FF + tx * 8 + j];
    }

    #pragma unroll
    for (int i = 0; i < 8; i++) {
        int n = nb + ty * 8 + i;
        float ps = 0.f, pd = 0.f;
        #pragma unroll
        for (int j = 0; j < 8; j++) { ps += acc[i][j] * asv[j]; pd += acc[i][j] * adv[j]; }
        // reduce across the 16 tx threads (each warp = two 16-lane tx groups)
        #pragma unroll
        for (int off = 8; off; off >>= 1) {
            ps += __shfl_down_sync(0xffffffffu, ps, off, 16);
            pd += __shfl_down_sync(0xffffffffu, pd, off, 16);
        }
        if (tx == 0) { sps[ty * 8 + i] = ps; spd[ty * 8 + i] = pd; }
        if (n < NN) {
            *(float4*)&g_lin[(size_t)n * HF + cb + tx * 8] =
                make_float4(acc[i][0], acc[i][1], acc[i][2], acc[i][3]);
            *(float4*)&g_lin[(size_t)n * HF + cb + tx * 8 + 4] =
                make_float4(acc[i][4], acc[i][5], acc[i][6], acc[i][7]);
        }
    }
    __syncthreads();
    if (tid < 128) {
        int n = nb + tid;
        if (n < NN) {
            g_as[n * HEADS + head] = sps[tid];
            g_ad[n * HEADS + head] = spd[tid];
        }
    }
}

// ---------------- K3: CSR build ----------------
__global__ void k3a_hist(const int* __restrict__ ei) {
    int e = blockIdx.x * 256 + threadIdx.x;
    if (e < EE) atomicAdd(&g_deg[ei[EE + e]], 1);
}

__global__ void k3b_scan() {
    int tid = threadIdx.x, lane = tid & 31, wid = tid >> 5;
    const int chunk = (NN + 1023) / 1024;   // 20
    int start = tid * chunk;
    int end = min(start + chunk, NN);
    int s = 0;
    for (int i = start; i < end; i++) s += g_deg[i];
    int v = s;
    #pragma unroll
    for (int off = 1; off < 32; off <<= 1) {
        int t = __shfl_up_sync(0xffffffffu, v, off);
        if (lane >= off) v += t;
    }
    __shared__ int wsum[32];
    if (lane == 31) wsum[wid] = v;
    __syncthreads();
    if (wid == 0) {
        int wv = wsum[lane];
        #pragma unroll
        for (int off = 1; off < 32; off <<= 1) {
            int t = __shfl_up_sync(0xffffffffu, wv, off);
            if (lane >= off) wv += t;
        }
        wsum[lane] = wv;
    }
    __syncthreads();
    int excl = v - s + (wid ? wsum[wid - 1] : 0);
    int run = excl;
    for (int i = start; i < end; i++) { g_off[i] = run; run += g_deg[i]; }
    if (tid == 1023) g_off[NN] = run;
}

__global__ void k3c_scatter(const int* __restrict__ ei) {
    int e = blockIdx.x * 256 + threadIdx.x;
    if (e < EE) {
        int d = ei[EE + e];
        int slot = g_off[d] + atomicAdd(&g_cur[d], 1);
        g_srcsorted[slot] = ei[e];
    }
}

// ---------------- K4: GAT aggregation (block per dst) + bn2 stats ----------------
__global__ void k4_gat(const float* __restrict__ gat_b) {
    int n = blockIdx.x;
    int tid = threadIdx.x;  // 128
    int lane = tid & 31, warp = tid >> 5;
    int beg = g_off[n], end = g_off[n + 1];

    __shared__ float s_mh[HEADS], s_sh[HEADS];
    __shared__ float s_red[HEADS][4];
    __shared__ int sh_src[128];
    __shared__ __align__(16) float sh_al[128][HEADS];
    __shared__ __align__(16) float s_out[HF];

    float4 ad4 = *(const float4*)&g_ad[n * HEADS];

    // pass 1: per-head max
    float4 mx = make_float4(-3.4e38f, -3.4e38f, -3.4e38f, -3.4e38f);
    for (int i = beg + tid; i < end; i += 128) {
        int s = g_srcsorted[i];
        float4 as4 = *(const float4*)&g_as[s * HEADS];
        float e0 = as4.x + ad4.x; e0 = e0 > 0.f ? e0 : 0.2f * e0;
        float e1 = as4.y + ad4.y; e1 = e1 > 0.f ? e1 : 0.2f * e1;
        float e2 = as4.z + ad4.z; e2 = e2 > 0.f ? e2 : 0.2f * e2;
        float e3 = as4.w + ad4.w; e3 = e3 > 0.f ? e3 : 0.2f * e3;
        mx.x = fmaxf(mx.x, e0); mx.y = fmaxf(mx.y, e1);
        mx.z = fmaxf(mx.z, e2); mx.w = fmaxf(mx.w, e3);
    }
    #pragma unroll
    for (int off = 16; off; off >>= 1) {
        mx.x = fmaxf(mx.x, __shfl_down_sync(0xffffffffu, mx.x, off));
        mx.y = fmaxf(mx.y, __shfl_down_sync(0xffffffffu, mx.y, off));
        mx.z = fmaxf(mx.z, __shfl_down_sync(0xffffffffu, mx.z, off));
        mx.w = fmaxf(mx.w, __shfl_down_sync(0xffffffffu, mx.w, off));
    }
    if (lane == 0) {
        s_red[0][warp] = mx.x; s_red[1][warp] = mx.y;
        s_red[2][warp] = mx.z; s_red[3][warp] = mx.w;
    }
    __syncthreads();
    if (tid < HEADS)
        s_mh[tid] = fmaxf(fmaxf(s_red[tid][0], s_red[tid][1]),
                          fmaxf(s_red[tid][2], s_red[tid][3]));
    __syncthreads();

    // pass 2: per-head sum of exp
    float4 sm = make_float4(0.f, 0.f, 0.f, 0.f);
    float4 mh = make_float4(s_mh[0], s_mh[1], s_mh[2], s_mh[3]);
    for (int i = beg + tid; i < end; i += 128) {
        int s = g_srcsorted[i];
        float4 as4 = *(const float4*)&g_as[s * HEADS];
        float e0 = as4.x + ad4.x; e0 = e0 > 0.f ? e0 : 0.2f * e0;
        float e1 = as4.y + ad4.y; e1 = e1 > 0.f ? e1 : 0.2f * e1;
        float e2 = as4.z + ad4.z; e2 = e2 > 0.f ? e2 : 0.2f * e2;
        float e3 = as4.w + ad4.w; e3 = e3 > 0.f ? e3 : 0.2f * e3;
        sm.x += __expf(e0 - mh.x); sm.y += __expf(e1 - mh.y);
        sm.z += __expf(e2 - mh.z); sm.w += __expf(e3 - mh.w);
    }
    #pragma unroll
    for (int off = 16; off; off >>= 1) {
        sm.x += __shfl_down_sync(0xffffffffu, sm.x, off);
        sm.y += __shfl_down_sync(0xffffffffu, sm.y, off);
        sm.z += __shfl_down_sync(0xffffffffu, sm.z, off);
        sm.w += __shfl_down_sync(0xffffffffu, sm.w, off);
    }
    __syncthreads();
    if (lane == 0) {
        s_red[0][warp] = sm.x; s_red[1][warp] = sm.y;
        s_red[2][warp] = sm.z; s_red[3][warp] = sm.w;
    }
    __syncthreads();
    if (tid < HEADS)
        s_sh[tid] = s_red[tid][0] + s_red[tid][1] + s_red[tid][2] + s_red[tid][3] + 1e-16f;
    __syncthreads();

    // pass 3: alpha-weighted gather; thread tid covers 4 consecutive cols of 512
    float4 racc = make_float4(0.f, 0.f, 0.f, 0.f);
    int hj = tid >> 5;  // head for my 4 columns
    float4 rs = make_float4(1.f / s_sh[0], 1.f / s_sh[1], 1.f / s_sh[2], 1.f / s_sh[3]);
    for (int base = beg; base < end; base += 128) {
        int i = base + tid;
        if (i < end) {
            int s = g_srcsorted[i];
            sh_src[tid] = s;
            float4 as4 = *(const float4*)&g_as[s * HEADS];
            float e0 = as4.x + ad4.x; e0 = e0 > 0.f ? e0 : 0.2f * e0;
            float e1 = as4.y + ad4.y; e1 = e1 > 0.f ? e1 : 0.2f * e1;
            float e2 = as4.z + ad4.z; e2 = e2 > 0.f ? e2 : 0.2f * e2;
            float e3 = as4.w + ad4.w; e3 = e3 > 0.f ? e3 : 0.2f * e3;
            float4 al = make_float4(__expf(e0 - mh.x) * rs.x, __expf(e1 - mh.y) * rs.y,
                                    __expf(e2 - mh.z) * rs.z, __expf(e3 - mh.w) * rs.w);
            *(float4*)&sh_al[tid][0] = al;
        }
        __syncthreads();
        int cnt = min(128, end - base);
        for (int k = 0; k < cnt; k++) {
            int s = sh_src[k];
            float al = sh_al[k][hj];
            float4 v = *(const float4*)&g_lin[(size_t)s * HF + tid * 4];
            racc.x += al * v.x; racc.y += al * v.y;
            racc.z += al * v.z; racc.w += al * v.w;
        }
        __syncthreads();
    }
    *(float4*)&s_out[tid * 4] = racc;
    __syncthreads();

    // head mean + bias + stats (tid covers feature tid of 128)
    float v = 0.25f * (s_out[tid] + s_out[tid + FF] + s_out[tid + 2 * FF] + s_out[tid + 3 * FF])
              + gat_b[tid];
    g_hgat[(size_t)n * FF + tid] = v;
    atomicAdd(&g_s2[tid], (double)v);
    atomicAdd(&g_q2[tid], (double)v * (double)v);
}

// ---------------- K5: bn2-normalize + gated_conv2 + bn3 stats ----------------
__global__ void k5_conv2(const float* __restrict__ w1, const float* __restrict__ b1,
                         const float* __restrict__ w2, const float* __restrict__ b2,
                         const float* __restrict__ w3, const float* __restrict__ b3) {
    __shared__ float s_w1[HID * HID * 3], s_w2[HID * HID * 3], s_w3[HID * HID * 3];
    __shared__ float s_b1[HID], s_b2[HID], s_b3[HID];
    __shared__ float s_m2[FF], s_r2[FF];
    __shared__ float s_x[4][HID][TT + 2];
    __shared__ float s_sum[HID], s_sq[HID];

    int tid = threadIdx.x;
    for (int i = tid; i < HID * HID * 3; i += 128) {
        s_w1[i] = w1[i]; s_w2[i] = w2[i]; s_w3[i] = w3[i];
    }
    if (tid < HID) {
        s_b1[tid] = b1[tid]; s_b2[tid] = b2[tid]; s_b3[tid] = b3[tid];
        s_sum[tid] = 0.f; s_sq[tid] = 0.f;
    }
    if (tid < FF) { s_m2[tid] = g_m2[tid]; s_r2[tid] = g_r2[tid]; }
    __syncthreads();

    int w = tid >> 5, l = tid & 31;
    int n = blockIdx.x * 4 + w;
    int t = l & 7, o0 = l >> 3;

    if (n < NN) {
        if (l < 16) { s_x[w][l][0] = 0.f; s_x[w][l][TT + 1] = 0.f; }
        #pragma unroll
        for (int j = 0; j < 4; j++) {
            int idx = l + 32 * j;
            float h = g_hgat[(size_t)n * FF + idx];
            s_x[w][idx >> 3][(idx & 7) + 1] = (h - s_m2[idx]) * s_r2[idx];
        }
        __syncwarp();

        #pragma unroll
        for (int j = 0; j < 4; j++) {
            int o = o0 + 4 * j;
            float p = s_b1[o], q = s_b2[o], r = s_b3[o];
            #pragma unroll
            for (int i = 0; i < HID; i++) {
                #pragma unroll
                for (int k = 0; k < 3; k++) {
                    float xv = s_x[w][i][t + k];
                    int wi = (o * HID + i) * 3 + k;
                    p += s_w1[wi] * xv;
                    q += s_w2[wi] * xv;
                    r += s_w3[wi] * xv;
                }
            }
            float sg = 1.f / (1.f + __expf(-q));
            float h = p * sg + r;
            h = h > 0.f ? h : 0.f;
            g_h2[(size_t)n * FF + o * TT + t] = h;
            atomicAdd(&s_sum[o], h);
            atomicAdd(&s_sq[o], h * h);
        }
    }
    __syncthreads();
    if (tid < HID) {
        atomicAdd(&g_s3[tid], (double)s_sum[tid]);
        atomicAdd(&g_q3[tid], (double)s_sq[tid]);
    }
}

// ---------------- K6: epilogue ----------------
__global__ void k6_out(const float* __restrict__ ow1, const float* __restrict__ ob1,
                       const float* __restrict__ ow2, const float* __restrict__ ob2,
                       float* __restrict__ out) {
    int n = blockIdx.x;
    int tid = threadIdx.x;  // 64
    __shared__ float z[HID];
    __shared__ float ws[2];
    if (tid < HID) {
        size_t idx = (size_t)n * FF + tid * TT + (TT - 1);
        float h = (g_h2[idx] - g_m3[tid]) * g_r3[tid] + g_res[idx];
        z[tid] = h > 0.f ? h : 0.f;
    }
    __syncthreads();
    float y = ob1[tid];
    #pragma unroll
    for (int o = 0; o < HID; o++) y += z[o] * ow1[o * 64 + tid];
    y = y > 0.f ? y : 0.f;
    float contrib = y * ow2[tid];
    for (int off = 16; off; off >>= 1)
        contrib += __shfl_down_sync(0xffffffffu, contrib, off);
    if ((tid & 31) == 0) ws[tid >> 5] = contrib;
    __syncthreads();
    if (tid == 0) out[n] = ws[0] + ws[1] + ob2[0];
}

// ---------------- launch ----------------
extern "C" void kernel_launch(void* const* d_in, const int* in_sizes, int n_in,
                              void* d_out, int out_size) {
    const float* X       = (const float*)d_in[0];
    const int*   ei      = (const int*)  d_in[1];
    const float* w_in    = (const float*)d_in[2];
    const float* b_in    = (const float*)d_in[3];
    const float* res_w   = (const float*)d_in[4];
    const float* res_b   = (const float*)d_in[5];
    const float* tg1_w1  = (const float*)d_in[6];
    const float* tg1_b1  = (const float*)d_in[7];
    const float* tg1_w2  = (const float*)d_in[8];
    const float* tg1_b2  = (const float*)d_in[9];
    const float* tg1_w3  = (const float*)d_in[10];
    const float* tg1_b3  = (const float*)d_in[11];
    const float* gat_w   = (const float*)d_in[12];
    const float* att_src = (const float*)d_in[13];
    const float* att_dst = (const float*)d_in[14];
    const float* gat_b   = (const float*)d_in[15];
    const float* tg2_w1  = (const float*)d_in[16];
    const float* tg2_b1  = (const float*)d_in[17];
    const float* tg2_w2  = (const float*)d_in[18];
    const float* tg2_b2  = (const float*)d_in[19];
    const float* tg2_w3  = (const float*)d_in[20];
    const float* tg2_b3  = (const float*)d_in[21];
    const float* out_w1  = (const float*)d_in[22];
    const float* out_b1  = (const float*)d_in[23];
    const float* out_w2  = (const float*)d_in[24];
    const float* out_b2  = (const float*)d_in[25];
    float* out = (float*)d_out;

    k0_zero<<<(NN + 255) / 256, 256>>>();
    k1_front<<<(NN + 3) / 4, 128>>>(X, w_in, b_in, res_w, res_b,
                                    tg1_w1, tg1_b1, tg1_w2, tg1_b2, tg1_w3, tg1_b3);
    k_fin<<<1, 128>>>(0);
    {
        dim3 grid(HEADS, (NN + 127) / 128);   // 4 x 157
        k2_gemm<<<grid, 256>>>(gat_w, att_src, att_dst);
    }
    k3a_hist<<<(EE + 255) / 256, 256>>>(ei);
    k3b_scan<<<1, 1024>>>();
    k3c_scatter<<<(EE + 255) / 256, 256>>>(ei);
    k4_gat<<<NN, 128>>>(gat_b);
    k_fin<<<1, 128>>>(1);
    k5_conv2<<<(NN + 3) / 4, 128>>>(tg2_w1, tg2_b1, tg2_w2, tg2_b2, tg2_w3, tg2_b3);
    k_fin<<<1, 128>>>(2);
    k6_out<<<NN, 64>>>(out_w1, out_b1, out_w2, out_b2, out);
}